// round 13
// baseline (speedup 1.0000x reference)
#include <cuda_runtime.h>
#include <cstdint>

// Problem sizes (fixed by dataset)
#define TOK    8192      // B*S
#define DDIM   1024
#define NPOOL  64
#define RDIM   128

// h partials: [4 n-quarters][TOK][RDIM]  (16 MB static device scratch)
__device__ float g_h[4u * TOK * RDIM];

// ---------------- helpers ----------------
__device__ __forceinline__ uint32_t smem_u32(const void* p) {
    uint32_t a;
    asm("{ .reg .u64 t; cvta.to.shared.u64 t, %1; cvt.u32.u64 %0, t; }" : "=r"(a) : "l"(p));
    return a;
}
__device__ __forceinline__ uint32_t f2tf32(float f) {
    uint32_t u;
    asm("cvt.rna.tf32.f32 %0, %1;" : "=r"(u) : "f"(f));
    return u;
}
__device__ __forceinline__ void cp_async16(uint32_t smem_dst, const void* gptr) {
    asm volatile("cp.async.cg.shared.global [%0], [%1], 16;" :: "r"(smem_dst), "l"(gptr) : "memory");
}
#define MBARRIER_INIT(addr, cnt) \
    asm volatile("mbarrier.init.shared.b64 [%0], %1;" :: "r"((uint32_t)(addr)), "r"((uint32_t)(cnt)) : "memory")
#define MBARRIER_ARRIVE(addr) \
    asm volatile("mbarrier.arrive.shared.b64 _, [%0];" :: "r"((uint32_t)(addr)) : "memory")
// .noinc is load-bearing: default form is count-neutral; .noinc contributes to expected count.
#define CP_MBAR_ARRIVE(addr) \
    asm volatile("cp.async.mbarrier.arrive.noinc.shared.b64 [%0];" :: "r"((uint32_t)(addr)) : "memory")

#define MBARRIER_WAIT_PARITY(addr, par) do { \
    uint32_t _m = (uint32_t)(addr), _p = (uint32_t)(par), _d; \
    asm volatile("{ .reg .pred p; mbarrier.try_wait.parity.acquire.cta.shared::cta.b64 p, [%1], %2; selp.b32 %0,1,0,p; }" \
        : "=r"(_d) : "r"(_m), "r"(_p) : "memory"); \
    if (!_d) { \
        asm volatile("{ .reg .pred P1; WL_%=: mbarrier.try_wait.parity.acquire.cta.shared::cta.b64 P1, [%0], %1, 0x989680; @P1 bra.uni WD_%=; bra.uni WL_%=; WD_%=: }" \
            :: "r"(_m), "r"(_p) : "memory"); \
    } } while (0)

__device__ __forceinline__ void mma_tf32(float* c, const uint32_t* a, uint32_t b0, uint32_t b1) {
    asm volatile(
        "mma.sync.aligned.m16n8k8.row.col.f32.tf32.tf32.f32 "
        "{%0,%1,%2,%3}, {%4,%5,%6,%7}, {%8,%9}, {%0,%1,%2,%3};"
        : "+f"(c[0]), "+f"(c[1]), "+f"(c[2]), "+f"(c[3])
        : "r"(a[0]), "r"(a[1]), "r"(a[2]), "r"(a[3]), "r"(b0), "r"(b1));
}

// Swizzled SMEM indexing (float units), conflict-free for all used patterns.
// A: [m][k], 128 x 32 ;  B: [k][n], 32 x 128
#define AIDX(m, k) ((m) * 32 + ((k) ^ (((m) & 7) << 2)))
#define BIDX(k, n) ((k) * 128 + ((n) ^ (((k) & 3) << 3)))

// SMEM: [0..1023] barriers (256 floats); then NST stages x 8192 floats (32KB):
//   A 4096 floats (128x32), B 4096 floats (32x128)
#define NST 3
#define SM_BASE(s) (256 + (s) * 8192)
#define SMEM_BYTES ((256 + NST * 8192) * 4)
// barrier byte offsets from smem base: full[s] = s*8 ; empty[s] = 64 + s*8

// ---------------- consumer compute core: 64x64 warp tile ----------------
struct Frag { float c[4][8][4]; };   // 128 accum regs

__device__ __forceinline__ void compute64(const uint32_t* __restrict__ As,
                                          const uint32_t* __restrict__ Bs,
                                          int rA, int ncol, int cA, int nB, int kB, Frag& F) {
    #pragma unroll
    for (int ks = 0; ks < 4; ++ks) {
        int k0 = ks * 8;
        uint32_t a[4][4];
        #pragma unroll
        for (int mt = 0; mt < 4; ++mt) {
            int m = rA + mt * 16;
            a[mt][0] = As[AIDX(m,     k0 + cA)];
            a[mt][1] = As[AIDX(m + 8, k0 + cA)];
            a[mt][2] = As[AIDX(m,     k0 + 4 + cA)];
            a[mt][3] = As[AIDX(m + 8, k0 + 4 + cA)];
        }
        #pragma unroll
        for (int np = 0; np < 4; ++np) {     // nt pairs: keeps live b-regs at 4
            uint32_t b[2][2];
            #pragma unroll
            for (int j = 0; j < 2; ++j) {
                int n = ncol + (np * 2 + j) * 8 + nB;
                b[j][0] = Bs[BIDX(k0 + kB,     n)];
                b[j][1] = Bs[BIDX(k0 + 4 + kB, n)];
            }
            #pragma unroll
            for (int j = 0; j < 2; ++j)
                #pragma unroll
                for (int mt = 0; mt < 4; ++mt)
                    mma_tf32(F.c[mt][np * 2 + j], a[mt], b[j][0], b[j][1]);
        }
    }
}

__device__ __forceinline__ void zero_frag(Frag& F) {
    #pragma unroll
    for (int mt = 0; mt < 4; ++mt)
        #pragma unroll
        for (int nt = 0; nt < 8; ++nt)
            #pragma unroll
            for (int q = 0; q < 4; ++q) F.c[mt][nt][q] = 0.f;
}

// ==================== Stage 1 ====================
// grid (64 token-tiles of 128, 4 n-quarters). C[128 tok,128 r] over K = 16 n * 1024 d.
// chunk c: d-block = c>>4 (outer), n = n0 + (c&15) (inner) -> x cached in producer regs
__global__ __launch_bounds__(192, 2)
void kc_stage1(const float* __restrict__ x, const float* __restrict__ fw,
               const float* __restrict__ FK) {
    extern __shared__ uint32_t smem[];
    uint32_t sb = smem_u32(smem);
    int tid = threadIdx.x, wid = tid >> 5, lane = tid & 31;
    int tok0 = blockIdx.x * 128;
    int n0 = blockIdx.y * 16;
    const int CHUNKS = 32 * 16;  // 512

    if (tid == 0) {
        #pragma unroll
        for (int s = 0; s < NST; ++s) {
            MBARRIER_INIT(sb + s * 8, 128);       // full: 64 STS-arrives + 64 cp-noinc
            MBARRIER_INIT(sb + 64 + s * 8, 128);  // empty: 128 consumer threads
        }
    }
    __syncthreads();

    if (wid >= 4) {
        // ---------------- producer (2 warps, 64 threads) ----------------
        int pt = tid - 128;          // 0..63
        int rbase = pt >> 2;         // 0..15 -> rows rbase + 16*p, p=0..7
        int cq = pt & 3;             // col quarter: float4 groups cq*2, cq*2+1
        float4 xc[8][2];             // x cache: 8 rows x 2 float4
        int st = 0, ph = 1;          // parity trick: first NST empty-waits pass
        for (int c = 0; c < CHUNKS; ++c) {
            int d0 = (c >> 4) * 32;
            int n = n0 + (c & 15);
            if ((c & 15) == 0) {
                #pragma unroll
                for (int p = 0; p < 8; ++p) {
                    const float* xp = &x[(size_t)(tok0 + rbase + 16 * p) * DDIM + d0 + cq * 8];
                    xc[p][0] = *(const float4*)&xp[0];
                    xc[p][1] = *(const float4*)&xp[4];
                }
            }
            MBARRIER_WAIT_PARITY(sb + 64 + st * 8, ph);
            uint32_t* A = smem + SM_BASE(st);
            #pragma unroll
            for (int p = 0; p < 8; ++p) {
                int m = rbase + 16 * p;
                float w = fw[(tok0 + m) * NPOOL + n];
                #pragma unroll
                for (int j = 0; j < 2; ++j) {
                    uint4 t4;
                    t4.x = f2tf32(xc[p][j].x * w); t4.y = f2tf32(xc[p][j].y * w);
                    t4.z = f2tf32(xc[p][j].z * w); t4.w = f2tf32(xc[p][j].w * w);
                    *(uint4*)&A[AIDX(m, cq * 8 + j * 4)] = t4;
                }
            }
            MBARRIER_ARRIVE(sb + st * 8);
            uint32_t bb = sb + 4u * (SM_BASE(st) + 4096);
            #pragma unroll
            for (int it = 0; it < 16; ++it) {
                int idx = pt + it * 64;
                int k = idx >> 5, q = idx & 31;
                cp_async16(bb + 4u * BIDX(k, q * 4),
                           &FK[((size_t)n * DDIM + d0 + k) * RDIM + q * 4]);
            }
            CP_MBAR_ARRIVE(sb + st * 8);
            if (++st == NST) { st = 0; ph ^= 1; }
        }
        return;
    }

    // ---------------- consumers (4 warps, 64x64 tiles: 2x2 bands) ----------------
    int mb = wid & 1, nb = wid >> 1;
    int rA = mb * 64 + (lane >> 2);
    int ncol = nb * 64;
    int cA = lane & 3, nB = lane >> 2, kB = lane & 3;
    Frag F;
    zero_frag(F);
    {
        int st = 0, ph = 0;
        for (int c = 0; c < CHUNKS; ++c) {
            MBARRIER_WAIT_PARITY(sb + st * 8, ph);
            compute64(smem + SM_BASE(st), smem + SM_BASE(st) + 4096, rA, ncol, cA, nB, kB, F);
            MBARRIER_ARRIVE(sb + 64 + st * 8);
            if (++st == NST) { st = 0; ph ^= 1; }
        }
    }
    // epilogue: write h partial
    {
        size_t hb = (size_t)blockIdx.y * TOK;
        #pragma unroll
        for (int mt = 0; mt < 4; ++mt) {
            int row = tok0 + mb * 64 + mt * 16 + (lane >> 2);
            #pragma unroll
            for (int nt = 0; nt < 8; ++nt) {
                int col = ncol + nt * 8 + (lane & 3) * 2;
                *(float2*)&g_h[(hb + row) * RDIM + col]     = make_float2(F.c[mt][nt][0], F.c[mt][nt][1]);
                *(float2*)&g_h[(hb + row + 8) * RDIM + col] = make_float2(F.c[mt][nt][2], F.c[mt][nt][3]);
            }
        }
    }
}

// ==================== Stage 2 ====================
// grid (64 token-tiles of 128, 8 d-tiles of 128). out over K = 64 n * 128 r.
// chunk c: r-block = c>>6 (outer), n = c&63 (inner) -> summed-h cached in producer regs
__global__ __launch_bounds__(192, 2)
void kc_stage2(const float* __restrict__ rw, const float* __restrict__ RK,
               float* __restrict__ out) {
    extern __shared__ uint32_t smem[];
    uint32_t sb = smem_u32(smem);
    int tid = threadIdx.x, wid = tid >> 5, lane = tid & 31;
    int tok0 = blockIdx.x * 128;
    int dt0 = blockIdx.y * 128;
    const int CHUNKS = 4 * 64;  // 256

    if (tid == 0) {
        #pragma unroll
        for (int s = 0; s < NST; ++s) {
            MBARRIER_INIT(sb + s * 8, 128);
            MBARRIER_INIT(sb + 64 + s * 8, 128);
        }
    }
    __syncthreads();

    if (wid >= 4) {
        // ---------------- producer (2 warps, 64 threads) ----------------
        int pt = tid - 128;
        int rbase = pt >> 2;
        int cq = pt & 3;
        float4 hc[8][2];             // summed h cache
        int st = 0, ph = 1;
        for (int c = 0; c < CHUNKS; ++c) {
            int r0 = (c >> 6) * 32;
            int n = c & 63;
            if ((c & 63) == 0) {
                #pragma unroll
                for (int p = 0; p < 8; ++p) {
                    size_t ho = (size_t)(tok0 + rbase + 16 * p) * RDIM + r0 + cq * 8;
                    #pragma unroll
                    for (int j = 0; j < 2; ++j) {
                        float4 v0 = *(const float4*)&g_h[ho + j * 4];
                        float4 v1 = *(const float4*)&g_h[1u * TOK * RDIM + ho + j * 4];
                        float4 v2 = *(const float4*)&g_h[2u * TOK * RDIM + ho + j * 4];
                        float4 v3 = *(const float4*)&g_h[3u * TOK * RDIM + ho + j * 4];
                        hc[p][j] = make_float4((v0.x + v1.x) + (v2.x + v3.x),
                                               (v0.y + v1.y) + (v2.y + v3.y),
                                               (v0.z + v1.z) + (v2.z + v3.z),
                                               (v0.w + v1.w) + (v2.w + v3.w));
                    }
                }
            }
            MBARRIER_WAIT_PARITY(sb + 64 + st * 8, ph);
            uint32_t* A = smem + SM_BASE(st);
            #pragma unroll
            for (int p = 0; p < 8; ++p) {
                int m = rbase + 16 * p;
                float w = rw[(tok0 + m) * NPOOL + n];
                #pragma unroll
                for (int j = 0; j < 2; ++j) {
                    uint4 t4;
                    t4.x = f2tf32(hc[p][j].x * w); t4.y = f2tf32(hc[p][j].y * w);
                    t4.z = f2tf32(hc[p][j].z * w); t4.w = f2tf32(hc[p][j].w * w);
                    *(uint4*)&A[AIDX(m, cq * 8 + j * 4)] = t4;
                }
            }
            MBARRIER_ARRIVE(sb + st * 8);
            uint32_t bb = sb + 4u * (SM_BASE(st) + 4096);
            #pragma unroll
            for (int it = 0; it < 16; ++it) {
                int idx = pt + it * 64;
                int k = idx >> 5, q = idx & 31;
                cp_async16(bb + 4u * BIDX(k, q * 4),
                           &RK[((size_t)n * RDIM + r0 + k) * DDIM + dt0 + q * 4]);
            }
            CP_MBAR_ARRIVE(sb + st * 8);
            if (++st == NST) { st = 0; ph ^= 1; }
        }
        return;
    }

    // ---------------- consumers (4 warps, 64x64 tiles: 2x2 bands) ----------------
    int mb = wid & 1, nb = wid >> 1;
    int rA = mb * 64 + (lane >> 2);
    int ncol = nb * 64;
    int cA = lane & 3, nB = lane >> 2, kB = lane & 3;
    Frag F;
    zero_frag(F);
    {
        int st = 0, ph = 0;
        for (int c = 0; c < CHUNKS; ++c) {
            MBARRIER_WAIT_PARITY(sb + st * 8, ph);
            compute64(smem + SM_BASE(st), smem + SM_BASE(st) + 4096, rA, ncol, cA, nB, kB, F);
            MBARRIER_ARRIVE(sb + 64 + st * 8);
            if (++st == NST) { st = 0; ph ^= 1; }
        }
    }
    // epilogue: write out
    {
        #pragma unroll
        for (int mt = 0; mt < 4; ++mt) {
            int row = tok0 + mb * 64 + mt * 16 + (lane >> 2);
            #pragma unroll
            for (int nt = 0; nt < 8; ++nt) {
                int col = dt0 + ncol + nt * 8 + (lane & 3) * 2;
                *(float2*)&out[(size_t)row * DDIM + col]       = make_float2(F.c[mt][nt][0], F.c[mt][nt][1]);
                *(float2*)&out[(size_t)(row + 8) * DDIM + col] = make_float2(F.c[mt][nt][2], F.c[mt][nt][3]);
            }
        }
    }
}

// ==================== launch ====================
extern "C" void kernel_launch(void* const* d_in, const int* in_sizes, int n_in,
                              void* d_out, int out_size) {
    const float* x  = (const float*)d_in[0];
    const float* fw = (const float*)d_in[1];
    const float* rw = (const float*)d_in[2];
    const float* FK = (const float*)d_in[3];
    const float* RK = (const float*)d_in[4];
    float* out = (float*)d_out;

    cudaFuncSetAttribute(kc_stage1, cudaFuncAttributeMaxDynamicSharedMemorySize, SMEM_BYTES);
    cudaFuncSetAttribute(kc_stage2, cudaFuncAttributeMaxDynamicSharedMemorySize, SMEM_BYTES);

    kc_stage1<<<dim3(64, 4), 192, SMEM_BYTES>>>(x, fw, FK);
    kc_stage2<<<dim3(64, 8), 192, SMEM_BYTES>>>(rw, RK, out);
}

// round 14
// speedup vs baseline: 1.1537x; 1.1537x over previous
#include <cuda_runtime.h>
#include <cstdint>

// Problem sizes (fixed by dataset)
#define TOK    8192      // B*S
#define DDIM   1024
#define NPOOL  64
#define RDIM   128

// h partials: [2 n-halves][TOK][RDIM]  (8 MB static device scratch)
__device__ float g_h[2u * TOK * RDIM];

// ---------------- helpers ----------------
__device__ __forceinline__ uint32_t smem_u32(const void* p) {
    uint32_t a;
    asm("{ .reg .u64 t; cvta.to.shared.u64 t, %1; cvt.u32.u64 %0, t; }" : "=r"(a) : "l"(p));
    return a;
}
__device__ __forceinline__ uint32_t f2tf32(float f) {
    uint32_t u;
    asm("cvt.rna.tf32.f32 %0, %1;" : "=r"(u) : "f"(f));
    return u;
}
__device__ __forceinline__ void cp_async16(uint32_t smem_dst, const void* gptr) {
    asm volatile("cp.async.cg.shared.global [%0], [%1], 16;" :: "r"(smem_dst), "l"(gptr) : "memory");
}
#define MBARRIER_INIT(addr, cnt) \
    asm volatile("mbarrier.init.shared.b64 [%0], %1;" :: "r"((uint32_t)(addr)), "r"((uint32_t)(cnt)) : "memory")
#define MBARRIER_ARRIVE(addr) \
    asm volatile("mbarrier.arrive.shared.b64 _, [%0];" :: "r"((uint32_t)(addr)) : "memory")
// .noinc is load-bearing: default form is count-neutral; .noinc contributes to expected count.
#define CP_MBAR_ARRIVE(addr) \
    asm volatile("cp.async.mbarrier.arrive.noinc.shared.b64 [%0];" :: "r"((uint32_t)(addr)) : "memory")

#define MBARRIER_WAIT_PARITY(addr, par) do { \
    uint32_t _m = (uint32_t)(addr), _p = (uint32_t)(par), _d; \
    asm volatile("{ .reg .pred p; mbarrier.try_wait.parity.acquire.cta.shared::cta.b64 p, [%1], %2; selp.b32 %0,1,0,p; }" \
        : "=r"(_d) : "r"(_m), "r"(_p) : "memory"); \
    if (!_d) { \
        asm volatile("{ .reg .pred P1; WL_%=: mbarrier.try_wait.parity.acquire.cta.shared::cta.b64 P1, [%0], %1, 0x989680; @P1 bra.uni WD_%=; bra.uni WL_%=; WD_%=: }" \
            :: "r"(_m), "r"(_p) : "memory"); \
    } } while (0)

__device__ __forceinline__ void mma_tf32(float* c, const uint32_t* a, uint32_t b0, uint32_t b1) {
    asm volatile(
        "mma.sync.aligned.m16n8k8.row.col.f32.tf32.tf32.f32 "
        "{%0,%1,%2,%3}, {%4,%5,%6,%7}, {%8,%9}, {%0,%1,%2,%3};"
        : "+f"(c[0]), "+f"(c[1]), "+f"(c[2]), "+f"(c[3])
        : "r"(a[0]), "r"(a[1]), "r"(a[2]), "r"(a[3]), "r"(b0), "r"(b1));
}

// Swizzled SMEM indexing (float units), conflict-free for all used patterns.
// A: [m][k], 128 x 64 ;  B: [k][n], 64 x 128
#define AIDX(m, k) ((m) * 64 + ((k) ^ (((m) & 7) << 2)))
#define BIDX(k, n) ((k) * 128 + ((n) ^ (((k) & 3) << 3)))

// SMEM: [0..1023] barriers (256 floats); then NST stages x 16384 floats (64KB):
//   A 8192 floats (128x64), B 8192 floats (64x128)
#define NST 3
#define SM_BASE(s) (256 + (s) * 16384)
#define SMEM_BYTES ((256 + NST * 16384) * 4)
// barrier byte offsets from smem base: full[s] = s*8 ; empty[s] = 64 + s*8

// ---------------- consumer compute core ----------------
// 8 consumer warps: rows band (wid&3)*32, cols band (wid>>2)*64. K=64 per chunk.
struct Frag { float c[2][8][4]; };

__device__ __forceinline__ void compute_chunk(const uint32_t* __restrict__ As,
                                              const uint32_t* __restrict__ Bs,
                                              int wid, int lane, Frag& F) {
    int ncol = (wid >> 2) * 64;
    int rA = (wid & 3) * 32 + (lane >> 2);
    int cA = lane & 3, nB = lane >> 2, kB = lane & 3;
    #pragma unroll
    for (int ks = 0; ks < 8; ++ks) {
        int k0 = ks * 8;
        uint32_t a[2][4], b[8][2];
        #pragma unroll
        for (int nt = 0; nt < 8; ++nt) {
            b[nt][0] = Bs[BIDX(k0 + kB,     ncol + nt * 8 + nB)];
            b[nt][1] = Bs[BIDX(k0 + 4 + kB, ncol + nt * 8 + nB)];
        }
        #pragma unroll
        for (int mt = 0; mt < 2; ++mt) {
            int m = rA + mt * 16;
            a[mt][0] = As[AIDX(m,     k0 + cA)];
            a[mt][1] = As[AIDX(m + 8, k0 + cA)];
            a[mt][2] = As[AIDX(m,     k0 + 4 + cA)];
            a[mt][3] = As[AIDX(m + 8, k0 + 4 + cA)];
        }
        #pragma unroll
        for (int nt = 0; nt < 8; ++nt) {
            mma_tf32(F.c[0][nt], a[0], b[nt][0], b[nt][1]);
            mma_tf32(F.c[1][nt], a[1], b[nt][0], b[nt][1]);
        }
    }
}

// ==================== Stage 1 ====================
// grid (64 token-tiles, 2 n-halves). C[128 tok,128 r] = sum_{n in half, d} (fw.x) @ FK
// chunk c: d-block = c>>4 (outer), n-pair = n0 + 2*(c&15) (inner); K=64 = 2n x 32d.
__global__ __launch_bounds__(384, 1)
void kc_stage1(const float* __restrict__ x, const float* __restrict__ fw,
               const float* __restrict__ FK) {
    extern __shared__ uint32_t smem[];
    uint32_t sb = smem_u32(smem);
    int tid = threadIdx.x, wid = tid >> 5, lane = tid & 31;
    int tok0 = blockIdx.x * 128;
    int n0 = blockIdx.y * 32;
    const int CHUNKS = 32 * 16;  // 512

    if (tid == 0) {
        #pragma unroll
        for (int s = 0; s < NST; ++s) {
            MBARRIER_INIT(sb + s * 8, 256);       // full: 128 STS-arrives + 128 cp-noinc
            MBARRIER_INIT(sb + 64 + s * 8, 256);  // empty: 256 consumer threads
        }
    }
    __syncthreads();

    if (wid >= 8) {
        // ---------------- producer (4 warps, 128 threads) ----------------
        int pt = tid - 256;          // 0..127
        int rbase = pt >> 3;         // 0..15 -> rows rbase + 16*p, p=0..7
        int g4 = (pt & 7) * 4;       // col group within 32 d
        float4 xc[8];
        int st = 0, ph = 1;          // parity trick: first NST empty-waits pass
        for (int c = 0; c < CHUNKS; ++c) {
            int d0 = (c >> 4) * 32;
            int n = n0 + 2 * (c & 15);
            if ((c & 15) == 0) {     // refresh x cache once per d-block
                #pragma unroll
                for (int p = 0; p < 8; ++p)
                    xc[p] = *(const float4*)&x[(size_t)(tok0 + rbase + 16 * p) * DDIM + d0 + g4];
            }
            MBARRIER_WAIT_PARITY(sb + 64 + st * 8, ph);
            uint32_t* A = smem + SM_BASE(st);
            #pragma unroll
            for (int p = 0; p < 8; ++p) {
                int m = rbase + 16 * p;
                float w0 = fw[(tok0 + m) * NPOOL + n];
                float w1 = fw[(tok0 + m) * NPOOL + n + 1];
                uint4 t4;
                t4.x = f2tf32(xc[p].x * w0); t4.y = f2tf32(xc[p].y * w0);
                t4.z = f2tf32(xc[p].z * w0); t4.w = f2tf32(xc[p].w * w0);
                *(uint4*)&A[AIDX(m, g4)] = t4;
                t4.x = f2tf32(xc[p].x * w1); t4.y = f2tf32(xc[p].y * w1);
                t4.z = f2tf32(xc[p].z * w1); t4.w = f2tf32(xc[p].w * w1);
                *(uint4*)&A[AIDX(m, 32 + g4)] = t4;
            }
            MBARRIER_ARRIVE(sb + st * 8);
            uint32_t bb = sb + 4u * (SM_BASE(st) + 8192);
            #pragma unroll
            for (int it = 0; it < 16; ++it) {
                int idx = pt + it * 128;            // 0..2047
                int k = idx >> 5, q = idx & 31;     // k: 0..63 (rows), q: n-group
                int nn = n + (k >> 5), kk = k & 31;
                cp_async16(bb + 4u * BIDX(k, q * 4),
                           &FK[((size_t)nn * DDIM + d0 + kk) * RDIM + q * 4]);
            }
            CP_MBAR_ARRIVE(sb + st * 8);
            if (++st == NST) { st = 0; ph ^= 1; }
        }
        return;
    }

    // ---------------- consumers (8 warps) ----------------
    Frag F;
    #pragma unroll
    for (int mt = 0; mt < 2; ++mt)
        #pragma unroll
        for (int nt = 0; nt < 8; ++nt)
            #pragma unroll
            for (int q = 0; q < 4; ++q) F.c[mt][nt][q] = 0.f;

    {
        int st = 0, ph = 0;
        for (int c = 0; c < CHUNKS; ++c) {
            MBARRIER_WAIT_PARITY(sb + st * 8, ph);
            compute_chunk(smem + SM_BASE(st), smem + SM_BASE(st) + 8192, wid, lane, F);
            MBARRIER_ARRIVE(sb + 64 + st * 8);
            if (++st == NST) { st = 0; ph ^= 1; }
        }
    }

    // epilogue: write h partial
    {
        int mrow = tok0 + (wid & 3) * 32;
        int ncol = (wid >> 2) * 64;
        size_t hb = (size_t)blockIdx.y * TOK;
        #pragma unroll
        for (int mt = 0; mt < 2; ++mt) {
            int row = mrow + mt * 16 + (lane >> 2);
            #pragma unroll
            for (int nt = 0; nt < 8; ++nt) {
                int col = ncol + nt * 8 + (lane & 3) * 2;
                *(float2*)&g_h[(hb + row) * RDIM + col]     = make_float2(F.c[mt][nt][0], F.c[mt][nt][1]);
                *(float2*)&g_h[(hb + row + 8) * RDIM + col] = make_float2(F.c[mt][nt][2], F.c[mt][nt][3]);
            }
        }
    }
}

// ==================== Stage 2 ====================
// grid (64 token-tiles, 8 d-tiles). out[128 tok,128 d] = sum_{n,r} (rw.(h0+h1)) @ RK
// chunk c: r-block = c>>5 (outer), n-pair = 2*(c&31) (inner); K=64 = 2n x 32r.
__global__ __launch_bounds__(384, 1)
void kc_stage2(const float* __restrict__ rw, const float* __restrict__ RK,
               float* __restrict__ out) {
    extern __shared__ uint32_t smem[];
    uint32_t sb = smem_u32(smem);
    int tid = threadIdx.x, wid = tid >> 5, lane = tid & 31;
    int tok0 = blockIdx.x * 128;
    int dt0 = blockIdx.y * 128;
    const int CHUNKS = 4 * 32;  // 128

    if (tid == 0) {
        #pragma unroll
        for (int s = 0; s < NST; ++s) {
            MBARRIER_INIT(sb + s * 8, 256);
            MBARRIER_INIT(sb + 64 + s * 8, 256);
        }
    }
    __syncthreads();

    if (wid >= 8) {
        // ---------------- producer ----------------
        int pt = tid - 256;
        int rbase = pt >> 3;
        int g4 = (pt & 7) * 4;
        float4 hc[8];
        int st = 0, ph = 1;
        for (int c = 0; c < CHUNKS; ++c) {
            int r0 = (c >> 5) * 32;
            int n = 2 * (c & 31);
            if ((c & 31) == 0) {     // refresh (h0+h1) cache once per r-block
                #pragma unroll
                for (int p = 0; p < 8; ++p) {
                    size_t ho = (size_t)(tok0 + rbase + 16 * p) * RDIM + r0 + g4;
                    float4 v0 = *(const float4*)&g_h[ho];
                    float4 v1 = *(const float4*)&g_h[(size_t)TOK * RDIM + ho];
                    hc[p] = make_float4(v0.x + v1.x, v0.y + v1.y, v0.z + v1.z, v0.w + v1.w);
                }
            }
            MBARRIER_WAIT_PARITY(sb + 64 + st * 8, ph);
            uint32_t* A = smem + SM_BASE(st);
            #pragma unroll
            for (int p = 0; p < 8; ++p) {
                int m = rbase + 16 * p;
                float w0 = rw[(tok0 + m) * NPOOL + n];
                float w1 = rw[(tok0 + m) * NPOOL + n + 1];
                uint4 t4;
                t4.x = f2tf32(hc[p].x * w0); t4.y = f2tf32(hc[p].y * w0);
                t4.z = f2tf32(hc[p].z * w0); t4.w = f2tf32(hc[p].w * w0);
                *(uint4*)&A[AIDX(m, g4)] = t4;
                t4.x = f2tf32(hc[p].x * w1); t4.y = f2tf32(hc[p].y * w1);
                t4.z = f2tf32(hc[p].z * w1); t4.w = f2tf32(hc[p].w * w1);
                *(uint4*)&A[AIDX(m, 32 + g4)] = t4;
            }
            MBARRIER_ARRIVE(sb + st * 8);
            uint32_t bb = sb + 4u * (SM_BASE(st) + 8192);
            #pragma unroll
            for (int it = 0; it < 16; ++it) {
                int idx = pt + it * 128;
                int k = idx >> 5, q = idx & 31;
                int nn = n + (k >> 5), kk = k & 31;
                cp_async16(bb + 4u * BIDX(k, q * 4),
                           &RK[((size_t)nn * RDIM + r0 + kk) * DDIM + dt0 + q * 4]);
            }
            CP_MBAR_ARRIVE(sb + st * 8);
            if (++st == NST) { st = 0; ph ^= 1; }
        }
        return;
    }

    // ---------------- consumers ----------------
    Frag F;
    #pragma unroll
    for (int mt = 0; mt < 2; ++mt)
        #pragma unroll
        for (int nt = 0; nt < 8; ++nt)
            #pragma unroll
            for (int q = 0; q < 4; ++q) F.c[mt][nt][q] = 0.f;

    {
        int st = 0, ph = 0;
        for (int c = 0; c < CHUNKS; ++c) {
            MBARRIER_WAIT_PARITY(sb + st * 8, ph);
            compute_chunk(smem + SM_BASE(st), smem + SM_BASE(st) + 8192, wid, lane, F);
            MBARRIER_ARRIVE(sb + 64 + st * 8);
            if (++st == NST) { st = 0; ph ^= 1; }
        }
    }

    // epilogue: write out
    {
        int mrow = tok0 + (wid & 3) * 32;
        int ncol = dt0 + (wid >> 2) * 64;
        #pragma unroll
        for (int mt = 0; mt < 2; ++mt) {
            int row = mrow + mt * 16 + (lane >> 2);
            #pragma unroll
            for (int nt = 0; nt < 8; ++nt) {
                int col = ncol + nt * 8 + (lane & 3) * 2;
                *(float2*)&out[(size_t)row * DDIM + col]       = make_float2(F.c[mt][nt][0], F.c[mt][nt][1]);
                *(float2*)&out[(size_t)(row + 8) * DDIM + col] = make_float2(F.c[mt][nt][2], F.c[mt][nt][3]);
            }
        }
    }
}

// ==================== launch ====================
extern "C" void kernel_launch(void* const* d_in, const int* in_sizes, int n_in,
                              void* d_out, int out_size) {
    const float* x  = (const float*)d_in[0];
    const float* fw = (const float*)d_in[1];
    const float* rw = (const float*)d_in[2];
    const float* FK = (const float*)d_in[3];
    const float* RK = (const float*)d_in[4];
    float* out = (float*)d_out;

    cudaFuncSetAttribute(kc_stage1, cudaFuncAttributeMaxDynamicSharedMemorySize, SMEM_BYTES);
    cudaFuncSetAttribute(kc_stage2, cudaFuncAttributeMaxDynamicSharedMemorySize, SMEM_BYTES);

    kc_stage1<<<dim3(64, 2), 384, SMEM_BYTES>>>(x, fw, FK);
    kc_stage2<<<dim3(64, 8), 384, SMEM_BYTES>>>(rw, RK, out);
}

// round 15
// speedup vs baseline: 1.8361x; 1.5915x over previous
#include <cuda_runtime.h>
#include <cuda_fp16.h>
#include <cstdint>

// Problem sizes (fixed by dataset)
#define TOK    8192      // B*S
#define DDIM   1024
#define NPOOL  64
#define RDIM   128

// h partials: [2 n-halves][TOK][RDIM]  (8 MB static device scratch)
__device__ float g_h[2u * TOK * RDIM];

// ---------------- helpers ----------------
__device__ __forceinline__ uint32_t smem_u32(const void* p) {
    uint32_t a;
    asm("{ .reg .u64 t; cvta.to.shared.u64 t, %1; cvt.u32.u64 %0, t; }" : "=r"(a) : "l"(p));
    return a;
}
// pack two f32 -> f16x2 (lo in lower 16 bits)
__device__ __forceinline__ uint32_t pack_h2(float lo, float hi) {
    uint32_t u;
    asm("cvt.rn.f16x2.f32 %0, %1, %2;" : "=r"(u) : "f"(hi), "f"(lo));
    return u;
}
#define MBARRIER_INIT(addr, cnt) \
    asm volatile("mbarrier.init.shared.b64 [%0], %1;" :: "r"((uint32_t)(addr)), "r"((uint32_t)(cnt)) : "memory")
#define MBARRIER_ARRIVE(addr) \
    asm volatile("mbarrier.arrive.shared.b64 _, [%0];" :: "r"((uint32_t)(addr)) : "memory")

#define MBARRIER_WAIT_PARITY(addr, par) do { \
    uint32_t _m = (uint32_t)(addr), _p = (uint32_t)(par), _d; \
    asm volatile("{ .reg .pred p; mbarrier.try_wait.parity.acquire.cta.shared::cta.b64 p, [%1], %2; selp.b32 %0,1,0,p; }" \
        : "=r"(_d) : "r"(_m), "r"(_p) : "memory"); \
    if (!_d) { \
        asm volatile("{ .reg .pred P1; WL_%=: mbarrier.try_wait.parity.acquire.cta.shared::cta.b64 P1, [%0], %1, 0x989680; @P1 bra.uni WD_%=; bra.uni WL_%=; WD_%=: }" \
            :: "r"(_m), "r"(_p) : "memory"); \
    } } while (0)

// fp16 MMA: m16n8k16, f32 accumulate
__device__ __forceinline__ void mma_f16(float* c, const uint32_t* a, uint32_t b0, uint32_t b1) {
    asm volatile(
        "mma.sync.aligned.m16n8k16.row.col.f32.f16.f16.f32 "
        "{%0,%1,%2,%3}, {%4,%5,%6,%7}, {%8,%9}, {%0,%1,%2,%3};"
        : "+f"(c[0]), "+f"(c[1]), "+f"(c[2]), "+f"(c[3])
        : "r"(a[0]), "r"(a[1]), "r"(a[2]), "r"(a[3]), "r"(b0), "r"(b1));
}

// Swizzled SMEM indexing in uint32 (=f16x2 pair) units. kp = k/2 (pair index).
// A: [m][kp], 128 x 32 ;  B: [kp][n], 32 x 128  -- same proven-conflict-free patterns as R9.
#define AIDX(m, kp) ((m) * 32 + ((kp) ^ (((m) & 7) << 2)))
#define BIDX(kp, n) ((kp) * 128 + ((n) ^ (((kp) & 3) << 3)))

// SMEM: [0..1023] barriers (256 u32); then NST stages x 8192 u32 (32KB):
//   A 4096 u32 (128 m x 32 kp), B 4096 u32 (32 kp x 128 n)
#define NST 4
#define SM_BASE(s) (256 + (s) * 8192)
#define SMEM_BYTES ((256 + NST * 8192) * 4)
// barrier byte offsets: full[s] = s*8 ; empty[s] = 64 + s*8

// ---------------- consumer compute core ----------------
// 8 consumer warps: rows band (wid&3)*32, cols band (wid>>2)*64. K=64 halfs (32 kp) per chunk.
struct Frag { float c[2][8][4]; };

__device__ __forceinline__ void compute_chunk(const uint32_t* __restrict__ As,
                                              const uint32_t* __restrict__ Bs,
                                              int wid, int lane, Frag& F) {
    int ncol = (wid >> 2) * 64;
    int rA = (wid & 3) * 32 + (lane >> 2);
    int cA = lane & 3, nB = lane >> 2, kB = lane & 3;
    #pragma unroll
    for (int ks = 0; ks < 4; ++ks) {        // 4 x K16 mma steps = 32 kp
        int kp0 = ks * 8;
        uint32_t a[2][4], b[8][2];
        #pragma unroll
        for (int nt = 0; nt < 8; ++nt) {
            b[nt][0] = Bs[BIDX(kp0 + kB,     ncol + nt * 8 + nB)];
            b[nt][1] = Bs[BIDX(kp0 + 4 + kB, ncol + nt * 8 + nB)];
        }
        #pragma unroll
        for (int mt = 0; mt < 2; ++mt) {
            int m = rA + mt * 16;
            a[mt][0] = As[AIDX(m,     kp0 + cA)];
            a[mt][1] = As[AIDX(m + 8, kp0 + cA)];
            a[mt][2] = As[AIDX(m,     kp0 + 4 + cA)];
            a[mt][3] = As[AIDX(m + 8, kp0 + 4 + cA)];
        }
        #pragma unroll
        for (int nt = 0; nt < 8; ++nt) {
            mma_f16(F.c[0][nt], a[0], b[nt][0], b[nt][1]);
            mma_f16(F.c[1][nt], a[1], b[nt][0], b[nt][1]);
        }
    }
}

// ==================== Stage 1 ====================
// grid (64 token-tiles, 2 n-halves). C[128 tok,128 r] = sum_{n in half, d} (fw.x) @ FK
// chunk c: d-block = c>>4 (outer, 32 d), n-pair = n0 + 2*(c&15); K=64 halfs = 2n x 32d.
__global__ __launch_bounds__(384, 1)
void kc_stage1(const float* __restrict__ x, const float* __restrict__ fw,
               const float* __restrict__ FK) {
    extern __shared__ uint32_t smem[];
    uint32_t sb = smem_u32(smem);
    int tid = threadIdx.x, wid = tid >> 5, lane = tid & 31;
    int tok0 = blockIdx.x * 128;
    int n0 = blockIdx.y * 32;
    const int CHUNKS = 32 * 16;  // 512

    if (tid == 0) {
        #pragma unroll
        for (int s = 0; s < NST; ++s) {
            MBARRIER_INIT(sb + s * 8, 128);       // full: 128 producer arrives
            MBARRIER_INIT(sb + 64 + s * 8, 256);  // empty: 256 consumer threads
        }
    }
    __syncthreads();

    if (wid >= 8) {
        // ---------------- producer (4 warps, 128 threads) ----------------
        int pt = tid - 256;          // 0..127
        int rbase = pt >> 3;         // 0..15 -> rows rbase + 16*p, p=0..7
        int g4 = (pt & 7) * 4;       // 4 d within the 32-d block
        int kpb = (pt & 7) * 2;      // pair column base for A
        float4 xc[8];
        int st = 0, ph = 1;          // parity trick: first NST empty-waits pass
        for (int c = 0; c < CHUNKS; ++c) {
            int d0 = (c >> 4) * 32;
            int n = n0 + 2 * (c & 15);
            if ((c & 15) == 0) {     // refresh x cache once per d-block
                #pragma unroll
                for (int p = 0; p < 8; ++p)
                    xc[p] = *(const float4*)&x[(size_t)(tok0 + rbase + 16 * p) * DDIM + d0 + g4];
            }
            MBARRIER_WAIT_PARITY(sb + 64 + st * 8, ph);
            uint32_t* A = smem + SM_BASE(st);
            #pragma unroll
            for (int p = 0; p < 8; ++p) {
                int m = rbase + 16 * p;
                float w0 = fw[(tok0 + m) * NPOOL + n];
                float w1 = fw[(tok0 + m) * NPOOL + n + 1];
                uint2 t;
                t.x = pack_h2(xc[p].x * w0, xc[p].y * w0);
                t.y = pack_h2(xc[p].z * w0, xc[p].w * w0);
                *(uint2*)&A[AIDX(m, kpb)] = t;
                t.x = pack_h2(xc[p].x * w1, xc[p].y * w1);
                t.y = pack_h2(xc[p].z * w1, xc[p].w * w1);
                *(uint2*)&A[AIDX(m, 16 + kpb)] = t;
            }
            // B: [kp][n], kp 0..15 from n, 16..31 from n+1; pairs = consecutive d at fixed r.
            uint32_t* B = smem + SM_BASE(st) + 4096;
            #pragma unroll
            for (int it = 0; it < 8; ++it) {
                int idx = pt + it * 128;            // 0..1023
                int kp = idx >> 5, q = idx & 31;
                int nn = n + (kp >> 4);
                int dd = d0 + 2 * (kp & 15);
                const float* s0 = &FK[((size_t)nn * DDIM + dd) * RDIM + q * 4];
                float4 v0 = *(const float4*)s0;
                float4 v1 = *(const float4*)(s0 + RDIM);
                uint4 t4;
                t4.x = pack_h2(v0.x, v1.x); t4.y = pack_h2(v0.y, v1.y);
                t4.z = pack_h2(v0.z, v1.z); t4.w = pack_h2(v0.w, v1.w);
                *(uint4*)&B[BIDX(kp, q * 4)] = t4;
            }
            MBARRIER_ARRIVE(sb + st * 8);
            if (++st == NST) { st = 0; ph ^= 1; }
        }
        return;
    }

    // ---------------- consumers (8 warps) ----------------
    Frag F;
    #pragma unroll
    for (int mt = 0; mt < 2; ++mt)
        #pragma unroll
        for (int nt = 0; nt < 8; ++nt)
            #pragma unroll
            for (int q = 0; q < 4; ++q) F.c[mt][nt][q] = 0.f;

    {
        int st = 0, ph = 0;
        for (int c = 0; c < CHUNKS; ++c) {
            MBARRIER_WAIT_PARITY(sb + st * 8, ph);
            compute_chunk(smem + SM_BASE(st), smem + SM_BASE(st) + 4096, wid, lane, F);
            MBARRIER_ARRIVE(sb + 64 + st * 8);
            if (++st == NST) { st = 0; ph ^= 1; }
        }
    }

    // epilogue: write h partial
    {
        int mrow = tok0 + (wid & 3) * 32;
        int ncol = (wid >> 2) * 64;
        size_t hb = (size_t)blockIdx.y * TOK;
        #pragma unroll
        for (int mt = 0; mt < 2; ++mt) {
            int row = mrow + mt * 16 + (lane >> 2);
            #pragma unroll
            for (int nt = 0; nt < 8; ++nt) {
                int col = ncol + nt * 8 + (lane & 3) * 2;
                *(float2*)&g_h[(hb + row) * RDIM + col]     = make_float2(F.c[mt][nt][0], F.c[mt][nt][1]);
                *(float2*)&g_h[(hb + row + 8) * RDIM + col] = make_float2(F.c[mt][nt][2], F.c[mt][nt][3]);
            }
        }
    }
}

// ==================== Stage 2 ====================
// grid (64 token-tiles, 8 d-tiles). out[128 tok,128 d] = sum_{n,r} (rw.(h0+h1)) @ RK
// chunk c: r-block = c>>5 (outer, 32 r), n-pair = 2*(c&31); K=64 halfs = 2n x 32r.
__global__ __launch_bounds__(384, 1)
void kc_stage2(const float* __restrict__ rw, const float* __restrict__ RK,
               float* __restrict__ out) {
    extern __shared__ uint32_t smem[];
    uint32_t sb = smem_u32(smem);
    int tid = threadIdx.x, wid = tid >> 5, lane = tid & 31;
    int tok0 = blockIdx.x * 128;
    int dt0 = blockIdx.y * 128;
    const int CHUNKS = 4 * 32;  // 128

    if (tid == 0) {
        #pragma unroll
        for (int s = 0; s < NST; ++s) {
            MBARRIER_INIT(sb + s * 8, 128);
            MBARRIER_INIT(sb + 64 + s * 8, 256);
        }
    }
    __syncthreads();

    if (wid >= 8) {
        // ---------------- producer ----------------
        int pt = tid - 256;
        int rbase = pt >> 3;
        int g4 = (pt & 7) * 4;
        int kpb = (pt & 7) * 2;
        float4 hc[8];
        int st = 0, ph = 1;
        for (int c = 0; c < CHUNKS; ++c) {
            int r0 = (c >> 5) * 32;
            int n = 2 * (c & 31);
            if ((c & 31) == 0) {     // refresh (h0+h1) cache once per r-block
                #pragma unroll
                for (int p = 0; p < 8; ++p) {
                    size_t ho = (size_t)(tok0 + rbase + 16 * p) * RDIM + r0 + g4;
                    float4 v0 = *(const float4*)&g_h[ho];
                    float4 v1 = *(const float4*)&g_h[(size_t)TOK * RDIM + ho];
                    hc[p] = make_float4(v0.x + v1.x, v0.y + v1.y, v0.z + v1.z, v0.w + v1.w);
                }
            }
            MBARRIER_WAIT_PARITY(sb + 64 + st * 8, ph);
            uint32_t* A = smem + SM_BASE(st);
            #pragma unroll
            for (int p = 0; p < 8; ++p) {
                int m = rbase + 16 * p;
                float w0 = rw[(tok0 + m) * NPOOL + n];
                float w1 = rw[(tok0 + m) * NPOOL + n + 1];
                uint2 t;
                t.x = pack_h2(hc[p].x * w0, hc[p].y * w0);
                t.y = pack_h2(hc[p].z * w0, hc[p].w * w0);
                *(uint2*)&A[AIDX(m, kpb)] = t;
                t.x = pack_h2(hc[p].x * w1, hc[p].y * w1);
                t.y = pack_h2(hc[p].z * w1, hc[p].w * w1);
                *(uint2*)&A[AIDX(m, 16 + kpb)] = t;
            }
            uint32_t* B = smem + SM_BASE(st) + 4096;
            #pragma unroll
            for (int it = 0; it < 8; ++it) {
                int idx = pt + it * 128;
                int kp = idx >> 5, q = idx & 31;
                int nn = n + (kp >> 4);
                int rr = r0 + 2 * (kp & 15);
                const float* s0 = &RK[((size_t)nn * RDIM + rr) * DDIM + dt0 + q * 4];
                float4 v0 = *(const float4*)s0;
                float4 v1 = *(const float4*)(s0 + DDIM);
                uint4 t4;
                t4.x = pack_h2(v0.x, v1.x); t4.y = pack_h2(v0.y, v1.y);
                t4.z = pack_h2(v0.z, v1.z); t4.w = pack_h2(v0.w, v1.w);
                *(uint4*)&B[BIDX(kp, q * 4)] = t4;
            }
            MBARRIER_ARRIVE(sb + st * 8);
            if (++st == NST) { st = 0; ph ^= 1; }
        }
        return;
    }

    // ---------------- consumers ----------------
    Frag F;
    #pragma unroll
    for (int mt = 0; mt < 2; ++mt)
        #pragma unroll
        for (int nt = 0; nt < 8; ++nt)
            #pragma unroll
            for (int q = 0; q < 4; ++q) F.c[mt][nt][q] = 0.f;

    {
        int st = 0, ph = 0;
        for (int c = 0; c < CHUNKS; ++c) {
            MBARRIER_WAIT_PARITY(sb + st * 8, ph);
            compute_chunk(smem + SM_BASE(st), smem + SM_BASE(st) + 4096, wid, lane, F);
            MBARRIER_ARRIVE(sb + 64 + st * 8);
            if (++st == NST) { st = 0; ph ^= 1; }
        }
    }

    // epilogue: write out
    {
        int mrow = tok0 + (wid & 3) * 32;
        int ncol = dt0 + (wid >> 2) * 64;
        #pragma unroll
        for (int mt = 0; mt < 2; ++mt) {
            int row = mrow + mt * 16 + (lane >> 2);
            #pragma unroll
            for (int nt = 0; nt < 8; ++nt) {
                int col = ncol + nt * 8 + (lane & 3) * 2;
                *(float2*)&out[(size_t)row * DDIM + col]       = make_float2(F.c[mt][nt][0], F.c[mt][nt][1]);
                *(float2*)&out[(size_t)(row + 8) * DDIM + col] = make_float2(F.c[mt][nt][2], F.c[mt][nt][3]);
            }
        }
    }
}

// ==================== launch ====================
extern "C" void kernel_launch(void* const* d_in, const int* in_sizes, int n_in,
                              void* d_out, int out_size) {
    const float* x  = (const float*)d_in[0];
    const float* fw = (const float*)d_in[1];
    const float* rw = (const float*)d_in[2];
    const float* FK = (const float*)d_in[3];
    const float* RK = (const float*)d_in[4];
    float* out = (float*)d_out;

    cudaFuncSetAttribute(kc_stage1, cudaFuncAttributeMaxDynamicSharedMemorySize, SMEM_BYTES);
    cudaFuncSetAttribute(kc_stage2, cudaFuncAttributeMaxDynamicSharedMemorySize, SMEM_BYTES);

    kc_stage1<<<dim3(64, 2), 384, SMEM_BYTES>>>(x, fw, FK);
    kc_stage2<<<dim3(64, 8), 384, SMEM_BYTES>>>(rw, RK, out);
}